// round 5
// baseline (speedup 1.0000x reference)
#include <cuda_runtime.h>

// Perona-Malik diffusion, 3 iterations fused in ONE kernel.
// Warp-register temporal pipeline (6 stages), 4 cols/lane via float4,
// horizontal via shuffles, vertical via register sliding window.
// R5: CHUNK=64 (warm-up amortized 24%->13.5% of steps), 64-thread blocks
// for fine-grained scheduling, warm-up/main loop split.

#define NB 16
#define H  1024
#define W  1024

#define HALO   8
#define OUTWC  112
#define NSTRIP 10
#define CHUNK  64
#define WPB    2

// scaled constants (power-of-2 folds are exact)
#define K2_64  0.16f            // 64 * kappa^2
#define K2E    0.16000064f      // 64 * (kappa^2 + eps)
#define DTC    0.00390625f      // DT / 64

__device__ __forceinline__ float4 mk4(float v) { return make_float4(v, v, v, v); }

struct Flux { float4 fx, fy; };

// flux (scaled by 8) at one row from input rows vm, vc, vp.
__device__ __forceinline__ Flux fluxrow(const float4 vm, const float4 vc,
                                        const float4 vp, const bool valid)
{
    const unsigned m = 0xffffffffu;
    const float a0 = vm.x + 2.f*vc.x + vp.x;
    const float a1 = vm.y + 2.f*vc.y + vp.y;
    const float a2 = vm.z + 2.f*vc.z + vp.z;
    const float a3 = vm.w + 2.f*vc.w + vp.w;
    const float b0 = vp.x - vm.x;
    const float b1 = vp.y - vm.y;
    const float b2 = vp.z - vm.z;
    const float b3 = vp.w - vm.w;
    const float aL = __shfl_up_sync(m, a3, 1);
    const float aR = __shfl_down_sync(m, a0, 1);
    const float bL = __shfl_up_sync(m, b3, 1);
    const float bR = __shfl_down_sync(m, b0, 1);
    const float gx0 = a1 - aL;                 // 8*gx
    const float gx1 = a2 - a0;
    const float gx2 = a3 - a1;
    const float gx3 = aR - a2;
    const float gy0 = bL + 2.f*b0 + b1;        // 8*gy
    const float gy1 = b0 + 2.f*b1 + b2;
    const float gy2 = b1 + 2.f*b2 + b3;
    const float gy3 = b2 + 2.f*b3 + bR;
    const float d0 = fmaf(gx0, gx0, fmaf(gy0, gy0, K2E));
    const float d1 = fmaf(gx1, gx1, fmaf(gy1, gy1, K2E));
    const float d2 = fmaf(gx2, gx2, fmaf(gy2, gy2, K2E));
    const float d3 = fmaf(gx3, gx3, fmaf(gy3, gy3, K2E));
    const float c0 = valid ? __fdividef(K2_64, d0) : 0.f;
    const float c1 = valid ? __fdividef(K2_64, d1) : 0.f;
    const float c2 = valid ? __fdividef(K2_64, d2) : 0.f;
    const float c3 = valid ? __fdividef(K2_64, d3) : 0.f;
    Flux f;
    f.fx = make_float4(c0*gx0, c1*gx1, c2*gx2, c3*gx3);   // 8*flux
    f.fy = make_float4(c0*gy0, c1*gy1, c2*gy2, c3*gy3);
    return f;
}

// out = base + (DT/64) * dsum8, from scaled flux rows f0,f1,f2.
__device__ __forceinline__ float4 updrow(const float4 base,
                                         const Flux f0, const Flux f1,
                                         const Flux f2, const bool valid)
{
    const unsigned m = 0xffffffffu;
    const float p0 = f0.fx.x + 2.f*f1.fx.x + f2.fx.x;
    const float p1 = f0.fx.y + 2.f*f1.fx.y + f2.fx.y;
    const float p2 = f0.fx.z + 2.f*f1.fx.z + f2.fx.z;
    const float p3 = f0.fx.w + 2.f*f1.fx.w + f2.fx.w;
    const float q0 = f2.fy.x - f0.fy.x;
    const float q1 = f2.fy.y - f0.fy.y;
    const float q2 = f2.fy.z - f0.fy.z;
    const float q3 = f2.fy.w - f0.fy.w;
    const float pL = __shfl_up_sync(m, p3, 1);
    const float pR = __shfl_down_sync(m, p0, 1);
    const float qL = __shfl_up_sync(m, q3, 1);
    const float qR = __shfl_down_sync(m, q0, 1);
    const float d0 = (p1 - pL) + (qL + 2.f*q0 + q1);
    const float d1 = (p2 - p0) + (q0 + 2.f*q1 + q2);
    const float d2 = (p3 - p1) + (q1 + 2.f*q2 + q3);
    const float d3 = (pR - p2) + (q2 + 2.f*q3 + qR);
    float4 o;
    o.x = valid ? fmaf(DTC, d0, base.x) : 0.f;
    o.y = valid ? fmaf(DTC, d1, base.y) : 0.f;
    o.z = valid ? fmaf(DTC, d2, base.z) : 0.f;
    o.w = valid ? fmaf(DTC, d3, base.w) : 0.f;
    return o;
}

// GUARD=true: boundary warps (x or y edge), full predication.
// GUARD=false: fully interior warps, no bounds checks, no selects.
template<bool GUARD>
__device__ __forceinline__ void run_strip(const float* __restrict__ img,
                                          float* __restrict__ op,
                                          const int x0, const int y0,
                                          const bool colv, const bool st_ok)
{
    auto load = [&](int y) -> float4 {
        if (GUARD) {
            if (colv && (unsigned)y < (unsigned)H)
                return __ldg(reinterpret_cast<const float4*>(img + (size_t)y * W + x0));
            return mk4(0.f);
        }
        return __ldg(reinterpret_cast<const float4*>(img + (size_t)y * W + x0));
    };
    auto rv = [&](int y) -> bool {
        return GUARD ? (colv && (unsigned)y < (unsigned)H) : true;
    };

    float4 i0 = load(y0 - 6);
    float4 i1 = load(y0 - 5);
    float4 i2 = load(y0 - 4);

    Flux zf; zf.fx = mk4(0.f); zf.fy = mk4(0.f);
    Flux  f1a = zf, f1b = zf, f2a = zf, f2b = zf, f3a = zf, f3b = zf;
    float4 o1a = mk4(0.f), o1b = o1a, o2a = o1a, o2b = o1a;

    // one pipeline step at row y (stages advance; o3 valid once y >= y0)
    auto step = [&](int y) -> float4 {
        const float4 inext = load(y + 7);

        const Flux   f1c = fluxrow(i0, i1, i2,         rv(y + 5));
        const float4 o1c = updrow (i0, f1a, f1b, f1c,  rv(y + 4));
        const Flux   f2c = fluxrow(o1a, o1b, o1c,      rv(y + 3));
        const float4 o2c = updrow (o1a, f2a, f2b, f2c, rv(y + 2));
        const Flux   f3c = fluxrow(o2a, o2b, o2c,      rv(y + 1));
        const float4 o3  = updrow (o2a, f3a, f3b, f3c, rv(y));

        i0 = i1; i1 = i2; i2 = inext;
        f1a = f1b; f1b = f1c;
        o1a = o1b; o1b = o1c;
        f2a = f2b; f2b = f2c;
        o2a = o2b; o2b = o2c;
        f3a = f3b; f3b = f3c;
        return o3;
    };

    // warm-up: 10 steps, nothing stored
    #pragma unroll 2
    for (int y = y0 - 10; y < y0; ++y)
        (void)step(y);

    // main: 64 producing steps
    float* orow = op + (size_t)y0 * W + x0;
    #pragma unroll 2
    for (int y = y0; y < y0 + CHUNK; ++y) {
        const float4 o3 = step(y);
        if (st_ok)
            *reinterpret_cast<float4*>(orow) = o3;
        orow += W;
    }
}

__global__ __launch_bounds__(32 * WPB)
void pm_fused3(const float* __restrict__ in, float* __restrict__ out)
{
    const int lane = threadIdx.x & 31;
    const int warp = threadIdx.x >> 5;
    const int bx   = blockIdx.x;

    const int x0 = bx * OUTWC - HALO + lane * 4;
    const int y0 = (blockIdx.y * WPB + warp) * CHUNK;

    const size_t plane = (size_t)blockIdx.z * (size_t)(H * W);
    const float* __restrict__ img = in  + plane;
    float*       __restrict__ op  = out + plane;

    const bool colv  = (x0 >= 0) && (x0 + 4 <= W);
    const bool st_ok = colv && (lane >= HALO / 4) && (lane < 32 - HALO / 4);

    // fully interior warp: rows [y0-6, y0+CHUNK+6] and all lanes' columns
    // inside the image.
    const bool interior = (bx >= 1) && (bx <= NSTRIP - 2) &&
                          (y0 >= 6) && (y0 + CHUNK + 6 < H);

    if (interior)
        run_strip<false>(img, op, x0, y0, true, st_ok);
    else
        run_strip<true>(img, op, x0, y0, colv, st_ok);
}

extern "C" void kernel_launch(void* const* d_in, const int* in_sizes, int n_in,
                              void* d_out, int out_size)
{
    const float* image = (const float*)d_in[0];
    float* out = (float*)d_out;

    dim3 block(32 * WPB, 1, 1);                       // 64 threads
    dim3 grid(NSTRIP, H / (CHUNK * WPB), NB);         // 10 x 8 x 16 = 1280

    pm_fused3<<<grid, block>>>(image, out);
}

// round 6
// speedup vs baseline: 1.1483x; 1.1483x over previous
#include <cuda_runtime.h>

// Perona-Malik diffusion, 3 iterations fused in ONE kernel.
// Warp-register temporal pipeline (6 stages), 4 cols/lane via float4,
// horizontal via shuffles, vertical via register sliding window.
// R6: R4 configuration (CHUNK=32, 128-thread blocks) + __launch_bounds__(128,4)
// register cap -> 16 warps/SM occupancy (was 12 at 148 regs).

#define NB 16
#define H  1024
#define W  1024

#define HALO   8
#define OUTWC  112
#define NSTRIP 10
#define CHUNK  32
#define WPB    4

// scaled constants (power-of-2 folds are exact)
#define K2_64  0.16f            // 64 * kappa^2
#define K2E    0.16000064f      // 64 * (kappa^2 + eps)
#define DTC    0.00390625f      // DT / 64

__device__ __forceinline__ float4 mk4(float v) { return make_float4(v, v, v, v); }

struct Flux { float4 fx, fy; };

// flux (scaled by 8) at one row from input rows vm, vc, vp.
__device__ __forceinline__ Flux fluxrow(const float4 vm, const float4 vc,
                                        const float4 vp, const bool valid)
{
    const unsigned m = 0xffffffffu;
    const float a0 = vm.x + 2.f*vc.x + vp.x;
    const float a1 = vm.y + 2.f*vc.y + vp.y;
    const float a2 = vm.z + 2.f*vc.z + vp.z;
    const float a3 = vm.w + 2.f*vc.w + vp.w;
    const float b0 = vp.x - vm.x;
    const float b1 = vp.y - vm.y;
    const float b2 = vp.z - vm.z;
    const float b3 = vp.w - vm.w;
    const float aL = __shfl_up_sync(m, a3, 1);
    const float aR = __shfl_down_sync(m, a0, 1);
    const float bL = __shfl_up_sync(m, b3, 1);
    const float bR = __shfl_down_sync(m, b0, 1);
    const float gx0 = a1 - aL;                 // 8*gx
    const float gx1 = a2 - a0;
    const float gx2 = a3 - a1;
    const float gx3 = aR - a2;
    const float gy0 = bL + 2.f*b0 + b1;        // 8*gy
    const float gy1 = b0 + 2.f*b1 + b2;
    const float gy2 = b1 + 2.f*b2 + b3;
    const float gy3 = b2 + 2.f*b3 + bR;
    const float d0 = fmaf(gx0, gx0, fmaf(gy0, gy0, K2E));
    const float d1 = fmaf(gx1, gx1, fmaf(gy1, gy1, K2E));
    const float d2 = fmaf(gx2, gx2, fmaf(gy2, gy2, K2E));
    const float d3 = fmaf(gx3, gx3, fmaf(gy3, gy3, K2E));
    const float c0 = valid ? __fdividef(K2_64, d0) : 0.f;
    const float c1 = valid ? __fdividef(K2_64, d1) : 0.f;
    const float c2 = valid ? __fdividef(K2_64, d2) : 0.f;
    const float c3 = valid ? __fdividef(K2_64, d3) : 0.f;
    Flux f;
    f.fx = make_float4(c0*gx0, c1*gx1, c2*gx2, c3*gx3);   // 8*flux
    f.fy = make_float4(c0*gy0, c1*gy1, c2*gy2, c3*gy3);
    return f;
}

// out = base + (DT/64) * dsum8, from scaled flux rows f0,f1,f2.
__device__ __forceinline__ float4 updrow(const float4 base,
                                         const Flux f0, const Flux f1,
                                         const Flux f2, const bool valid)
{
    const unsigned m = 0xffffffffu;
    const float p0 = f0.fx.x + 2.f*f1.fx.x + f2.fx.x;
    const float p1 = f0.fx.y + 2.f*f1.fx.y + f2.fx.y;
    const float p2 = f0.fx.z + 2.f*f1.fx.z + f2.fx.z;
    const float p3 = f0.fx.w + 2.f*f1.fx.w + f2.fx.w;
    const float q0 = f2.fy.x - f0.fy.x;
    const float q1 = f2.fy.y - f0.fy.y;
    const float q2 = f2.fy.z - f0.fy.z;
    const float q3 = f2.fy.w - f0.fy.w;
    const float pL = __shfl_up_sync(m, p3, 1);
    const float pR = __shfl_down_sync(m, p0, 1);
    const float qL = __shfl_up_sync(m, q3, 1);
    const float qR = __shfl_down_sync(m, q0, 1);
    const float d0 = (p1 - pL) + (qL + 2.f*q0 + q1);
    const float d1 = (p2 - p0) + (q0 + 2.f*q1 + q2);
    const float d2 = (p3 - p1) + (q1 + 2.f*q2 + q3);
    const float d3 = (pR - p2) + (q2 + 2.f*q3 + qR);
    float4 o;
    o.x = valid ? fmaf(DTC, d0, base.x) : 0.f;
    o.y = valid ? fmaf(DTC, d1, base.y) : 0.f;
    o.z = valid ? fmaf(DTC, d2, base.z) : 0.f;
    o.w = valid ? fmaf(DTC, d3, base.w) : 0.f;
    return o;
}

// GUARD=true: boundary warps (x or y edge), full predication.
// GUARD=false: fully interior warps, no bounds checks, no selects.
template<bool GUARD>
__device__ __forceinline__ void run_strip(const float* __restrict__ img,
                                          float* __restrict__ op,
                                          const int x0, const int y0,
                                          const bool colv, const bool st_ok)
{
    auto load = [&](int y) -> float4 {
        if (GUARD) {
            if (colv && (unsigned)y < (unsigned)H)
                return __ldg(reinterpret_cast<const float4*>(img + (size_t)y * W + x0));
            return mk4(0.f);
        }
        return __ldg(reinterpret_cast<const float4*>(img + (size_t)y * W + x0));
    };
    auto rv = [&](int y) -> bool {
        return GUARD ? (colv && (unsigned)y < (unsigned)H) : true;
    };

    float4 i0 = load(y0 - 6);
    float4 i1 = load(y0 - 5);
    float4 i2 = load(y0 - 4);

    Flux zf; zf.fx = mk4(0.f); zf.fy = mk4(0.f);
    Flux  f1a = zf, f1b = zf, f2a = zf, f2b = zf, f3a = zf, f3b = zf;
    float4 o1a = mk4(0.f), o1b = o1a, o2a = o1a, o2b = o1a;

    #pragma unroll 2
    for (int y = y0 - 10; y < y0 + CHUNK; ++y) {
        const float4 inext = load(y + 7);

        const Flux   f1c = fluxrow(i0, i1, i2,         rv(y + 5));
        const float4 o1c = updrow (i0, f1a, f1b, f1c,  rv(y + 4));
        const Flux   f2c = fluxrow(o1a, o1b, o1c,      rv(y + 3));
        const float4 o2c = updrow (o1a, f2a, f2b, f2c, rv(y + 2));
        const Flux   f3c = fluxrow(o2a, o2b, o2c,      rv(y + 1));
        const float4 o3  = updrow (o2a, f3a, f3b, f3c, rv(y));

        if (st_ok && y >= y0)
            *reinterpret_cast<float4*>(op + (size_t)y * W + x0) = o3;

        i0 = i1; i1 = i2; i2 = inext;
        f1a = f1b; f1b = f1c;
        o1a = o1b; o1b = o1c;
        f2a = f2b; f2b = f2c;
        o2a = o2b; o2b = o2c;
        f3a = f3b; f3b = f3c;
    }
}

__global__ __launch_bounds__(128, 4)
void pm_fused3(const float* __restrict__ in, float* __restrict__ out)
{
    const int lane = threadIdx.x & 31;
    const int warp = threadIdx.x >> 5;
    const int bx   = blockIdx.x;

    const int x0 = bx * OUTWC - HALO + lane * 4;
    const int y0 = (blockIdx.y * WPB + warp) * CHUNK;

    const size_t plane = (size_t)blockIdx.z * (size_t)(H * W);
    const float* __restrict__ img = in  + plane;
    float*       __restrict__ op  = out + plane;

    const bool colv  = (x0 >= 0) && (x0 + 4 <= W);
    const bool st_ok = colv && (lane >= HALO / 4) && (lane < 32 - HALO / 4);

    // fully interior warp: all loads in rows [y0-6, y0+CHUNK+6] and all
    // lanes' columns inside the image.
    const bool interior = (bx >= 1) && (bx <= NSTRIP - 2) &&
                          (y0 >= 6) && (y0 + CHUNK + 6 < H);

    if (interior)
        run_strip<false>(img, op, x0, y0, true, st_ok);
    else
        run_strip<true>(img, op, x0, y0, colv, st_ok);
}

extern "C" void kernel_launch(void* const* d_in, const int* in_sizes, int n_in,
                              void* d_out, int out_size)
{
    const float* image = (const float*)d_in[0];
    float* out = (float*)d_out;

    dim3 block(32 * WPB, 1, 1);                  // 128 threads
    dim3 grid(NSTRIP, H / (CHUNK * WPB), NB);    // 10 x 8 x 16 = 1280 blocks

    pm_fused3<<<grid, block>>>(image, out);
}